// round 5
// baseline (speedup 1.0000x reference)
#include <cuda_runtime.h>
#include <stdint.h>

#define BB 8
#define HH 384
#define WW 1280
#define CC 3
#define NN (HH * WW)

// Packed z-buffer: high 32 bits = float bits of z (positive => order-preserving),
// low 32 bits = source point index (tie-break: min index), sentinel = all ones.
__device__ unsigned long long g_zbuf[BB * NN];
__device__ float g_rot[BB * 9];
__device__ float g_tr[BB * 3];

// No-FMA 3-term dot (XLA elementwise loop fusion of tiny dot: mul/add, no contract):
//   rn(rn(rn(a0*b0) + rn(a1*b1)) + rn(a2*b2))
__device__ __forceinline__ float dot3_nofma(float a0, float a1, float a2,
                                            float b0, float b1, float b2) {
    return __fadd_rn(__fadd_rn(__fmul_rn(a0, b0), __fmul_rn(a1, b1)),
                     __fmul_rn(a2, b2));
}

// FMA ascending-k dot (gemm path: acc = fma(ak, bk, acc)):
//   fma(a2,b2, fma(a1,b1, rn(a0*b0)))
__device__ __forceinline__ float dot3_fma(float a0, float a1, float a2,
                                          float b0, float b1, float b2) {
    return fmaf(a2, b2, fmaf(a1, b1, __fmul_rn(a0, b0)));
}

__global__ void setup_kernel(const float* __restrict__ pose,
                             const float* __restrict__ K,
                             const float* __restrict__ Kinv) {
    int b = threadIdx.x;
    if (b >= BB) return;
    const float* P  = pose + b * 12;  // (3,4) row-major
    const float* Kb = K    + b * 9;
    const float* Ki = Kinv + b * 9;

    // M1 = K @ R   (R = pose[:, :3]) -- gemm path: FMA chain
    float M1[9];
#pragma unroll
    for (int i = 0; i < 3; i++)
#pragma unroll
        for (int j = 0; j < 3; j++)
            M1[i * 3 + j] = dot3_fma(Kb[i * 3 + 0], Kb[i * 3 + 1], Kb[i * 3 + 2],
                                     P[0 * 4 + j], P[1 * 4 + j], P[2 * 4 + j]);
    // rot = M1 @ Kinv -- gemm path: FMA chain
#pragma unroll
    for (int i = 0; i < 3; i++)
#pragma unroll
        for (int j = 0; j < 3; j++)
            g_rot[b * 9 + i * 3 + j] =
                dot3_fma(M1[i * 3 + 0], M1[i * 3 + 1], M1[i * 3 + 2],
                         Ki[0 * 3 + j], Ki[1 * 3 + j], Ki[2 * 3 + j]);
    // tr = K @ t   (t = pose[:, 3]) -- gemm path: FMA chain
#pragma unroll
    for (int i = 0; i < 3; i++)
        g_tr[b * 3 + i] = dot3_fma(Kb[i * 3 + 0], Kb[i * 3 + 1], Kb[i * 3 + 2],
                                   P[0 * 4 + 3], P[1 * 4 + 3], P[2 * 4 + 3]);
}

__global__ void init_kernel() {
    int idx = blockIdx.x * blockDim.x + threadIdx.x;
    if (idx < BB * NN) g_zbuf[idx] = 0xFFFFFFFFFFFFFFFFULL;
}

__global__ void splat_kernel(const float* __restrict__ depth) {
    int pid = blockIdx.x * blockDim.x + threadIdx.x;
    int b = blockIdx.y;
    if (pid >= NN) return;

    float d = depth[(size_t)b * NN + pid];
    float jx = (float)(pid % WW);  // column (x)
    float iy = (float)(pid / WW);  // row (y)

    const float* R = g_rot + b * 9;
    const float* T = g_tr + b * 3;

    // point_cloud = index * depth (separate rounded multiply, as in ref)
    float px = __fmul_rn(jx, d);
    float py = __fmul_rn(iy, d);
    float pz = d;

    // tp = rot @ pc -- fused tiny dot: no-FMA mul/add chain; + tr separate add
    float x = __fadd_rn(dot3_nofma(R[0], R[1], R[2], px, py, pz), T[0]);
    float y = __fadd_rn(dot3_nofma(R[3], R[4], R[5], px, py, pz), T[1]);
    float z = __fadd_rn(dot3_nofma(R[6], R[7], R[8], px, py, pz), T[2]);

    const float eps = 1e-3f;
    float zs = fmaxf(z, eps);
    // IEEE correctly-rounded divide; rintf = round-half-even = jnp.round
    int u = (int)rintf(__fdiv_rn(x, zs));
    int v = (int)rintf(__fdiv_rn(y, zs));

    if (z > eps && u >= 0 && u < WW && v >= 0 && v < HH) {
        unsigned long long key =
            ((unsigned long long)__float_as_uint(z) << 32) | (unsigned)pid;
        atomicMin(&g_zbuf[(size_t)b * NN + v * WW + u], key);
    }
}

__global__ void resolve_kernel(const float* __restrict__ img,
                               float* __restrict__ out) {
    int pid = blockIdx.x * blockDim.x + threadIdx.x;
    int b = blockIdx.y;
    if (pid >= NN) return;

    unsigned long long key = g_zbuf[(size_t)b * NN + pid];
    unsigned idx = (unsigned)(key & 0xFFFFFFFFu);
    float z = __uint_as_float((unsigned)(key >> 32));

    float c0 = 0.0f, c1 = 0.0f, c2 = 0.0f, dep = 0.0f;
    if (idx < (unsigned)NN) {
        const float* ib = img + (size_t)b * CC * NN;
        c0 = ib[idx];
        c1 = ib[NN + idx];
        c2 = ib[2 * NN + idx];
        dep = z;
    }

    float* wi = out + (size_t)b * CC * NN;
    wi[pid]          = c0;
    wi[NN + pid]     = c1;
    wi[2 * NN + pid] = c2;
    out[(size_t)BB * CC * NN + (size_t)b * NN + pid] = dep;
}

extern "C" void kernel_launch(void* const* d_in, const int* in_sizes, int n_in,
                              void* d_out, int out_size) {
    const float* depth = (const float*)d_in[0];  // (B,H,W)
    const float* img   = (const float*)d_in[1];  // (B,C,H,W)
    const float* pose  = (const float*)d_in[2];  // (B,3,4)
    const float* K     = (const float*)d_in[3];  // (B,3,3)
    const float* Kinv  = (const float*)d_in[4];  // (B,3,3)
    float* out = (float*)d_out;                  // wimg (B,C,H,W) then wdepth (B,H,W)

    setup_kernel<<<1, 32>>>(pose, K, Kinv);

    int threads = 256;
    int blocks_flat = (BB * NN + threads - 1) / threads;
    init_kernel<<<blocks_flat, threads>>>();

    dim3 grid((NN + threads - 1) / threads, BB);
    splat_kernel<<<grid, threads>>>(depth);
    resolve_kernel<<<grid, threads>>>(img, out);
}

// round 6
// speedup vs baseline: 1.0640x; 1.0640x over previous
#include <cuda_runtime.h>
#include <stdint.h>

#define BB 8
#define HH 384
#define WW 1280
#define CC 3
#define NN (HH * WW)

// Inverted packed z-buffer. Logical key = (float_bits(z) << 32) | src_idx,
// winner = min key (min z, tie -> min idx). We store ~key and take atomicMax,
// so the "empty" sentinel is 0 == CUDA's static zero-init of device globals.
// resolve resets entries to 0 after reading, so every graph replay starts clean.
// A valid ~key is never 0 (needs z-bits==0xFFFFFFFF == NaN, excluded by z>eps).
__device__ __align__(16) unsigned long long g_zbuf[BB * NN];

// No-FMA 3-term dot (XLA fused elementwise lowering of the big dot):
//   rn(rn(rn(a0*b0) + rn(a1*b1)) + rn(a2*b2))
__device__ __forceinline__ float dot3_nofma(float a0, float a1, float a2,
                                            float b0, float b1, float b2) {
    return __fadd_rn(__fadd_rn(__fmul_rn(a0, b0), __fmul_rn(a1, b1)),
                     __fmul_rn(a2, b2));
}

// FMA ascending-k dot (gemm path for the tiny 3x3 setup matmuls):
//   fma(a2,b2, fma(a1,b1, rn(a0*b0)))
__device__ __forceinline__ float dot3_fma(float a0, float a1, float a2,
                                          float b0, float b1, float b2) {
    return fmaf(a2, b2, fmaf(a1, b1, __fmul_rn(a0, b0)));
}

__global__ void splat_kernel(const float* __restrict__ depth,
                             const float* __restrict__ pose,
                             const float* __restrict__ K,
                             const float* __restrict__ Kinv) {
    __shared__ float sR[9];
    __shared__ float sT[3];
    int b = blockIdx.y;

    if (threadIdx.x == 0) {
        const float* P  = pose + b * 12;  // (3,4)
        const float* Kb = K    + b * 9;
        const float* Ki = Kinv + b * 9;
        float M1[9];
#pragma unroll
        for (int i = 0; i < 3; i++)
#pragma unroll
            for (int j = 0; j < 3; j++)
                M1[i * 3 + j] = dot3_fma(Kb[i*3+0], Kb[i*3+1], Kb[i*3+2],
                                         P[0*4+j], P[1*4+j], P[2*4+j]);
#pragma unroll
        for (int i = 0; i < 3; i++)
#pragma unroll
            for (int j = 0; j < 3; j++)
                sR[i * 3 + j] = dot3_fma(M1[i*3+0], M1[i*3+1], M1[i*3+2],
                                         Ki[0*3+j], Ki[1*3+j], Ki[2*3+j]);
#pragma unroll
        for (int i = 0; i < 3; i++)
            sT[i] = dot3_fma(Kb[i*3+0], Kb[i*3+1], Kb[i*3+2],
                             P[0*4+3], P[1*4+3], P[2*4+3]);
    }
    __syncthreads();

    int pid = blockIdx.x * blockDim.x + threadIdx.x;
    if (pid >= NN) return;

    float d = depth[(size_t)b * NN + pid];
    float jx = (float)(pid % WW);  // column (x)
    float iy = (float)(pid / WW);  // row (y)

    // point_cloud = index * depth (separate rounded multiply)
    float px = __fmul_rn(jx, d);
    float py = __fmul_rn(iy, d);
    float pz = d;

    // tp = rot @ pc (no-FMA fused dot) + tr (separate rounded add)
    float x = __fadd_rn(dot3_nofma(sR[0], sR[1], sR[2], px, py, pz), sT[0]);
    float y = __fadd_rn(dot3_nofma(sR[3], sR[4], sR[5], px, py, pz), sT[1]);
    float z = __fadd_rn(dot3_nofma(sR[6], sR[7], sR[8], px, py, pz), sT[2]);

    const float eps = 1e-3f;
    float zs = fmaxf(z, eps);
    int u = (int)rintf(__fdiv_rn(x, zs));  // rintf = half-even = jnp.round
    int v = (int)rintf(__fdiv_rn(y, zs));

    if (z > eps && u >= 0 && u < WW && v >= 0 && v < HH) {
        unsigned long long key =
            ((unsigned long long)__float_as_uint(z) << 32) | (unsigned)pid;
        atomicMax(&g_zbuf[(size_t)b * NN + v * WW + u], ~key);
    }
}

// 2 pixels per thread: 16B zbuf load + 16B reset store, float2 output stores.
__global__ void resolve_kernel(const float* __restrict__ img,
                               float* __restrict__ out) {
    int t = blockIdx.x * blockDim.x + threadIdx.x;
    int b = blockIdx.y;
    int pid = t * 2;
    if (pid >= NN) return;

    unsigned long long* zp = &g_zbuf[(size_t)b * NN + pid];
    ulonglong2 ik = *reinterpret_cast<ulonglong2*>(zp);
    *reinterpret_cast<ulonglong2*>(zp) = make_ulonglong2(0ULL, 0ULL);  // reset

    const float* ib = img + (size_t)b * CC * NN;

    float2 c0 = make_float2(0.f, 0.f);
    float2 c1 = make_float2(0.f, 0.f);
    float2 c2 = make_float2(0.f, 0.f);
    float2 dep = make_float2(0.f, 0.f);

    if (ik.x) {
        unsigned long long key = ~ik.x;
        unsigned idx = (unsigned)key;
        c0.x = __ldg(&ib[idx]);
        c1.x = __ldg(&ib[NN + idx]);
        c2.x = __ldg(&ib[2 * NN + idx]);
        dep.x = __uint_as_float((unsigned)(key >> 32));
    }
    if (ik.y) {
        unsigned long long key = ~ik.y;
        unsigned idx = (unsigned)key;
        c0.y = __ldg(&ib[idx]);
        c1.y = __ldg(&ib[NN + idx]);
        c2.y = __ldg(&ib[2 * NN + idx]);
        dep.y = __uint_as_float((unsigned)(key >> 32));
    }

    float* wi = out + (size_t)b * CC * NN;
    *reinterpret_cast<float2*>(&wi[pid])          = c0;
    *reinterpret_cast<float2*>(&wi[NN + pid])     = c1;
    *reinterpret_cast<float2*>(&wi[2 * NN + pid]) = c2;
    *reinterpret_cast<float2*>(&out[(size_t)BB * CC * NN + (size_t)b * NN + pid]) = dep;
}

extern "C" void kernel_launch(void* const* d_in, const int* in_sizes, int n_in,
                              void* d_out, int out_size) {
    const float* depth = (const float*)d_in[0];  // (B,H,W)
    const float* img   = (const float*)d_in[1];  // (B,C,H,W)
    const float* pose  = (const float*)d_in[2];  // (B,3,4)
    const float* K     = (const float*)d_in[3];  // (B,3,3)
    const float* Kinv  = (const float*)d_in[4];  // (B,3,3)
    float* out = (float*)d_out;                  // wimg (B,C,H,W) then wdepth (B,H,W)

    int threads = 256;
    dim3 grid_splat((NN + threads - 1) / threads, BB);
    splat_kernel<<<grid_splat, threads>>>(depth, pose, K, Kinv);

    dim3 grid_res((NN / 2 + threads - 1) / threads, BB);
    resolve_kernel<<<grid_res, threads>>>(img, out);
}